// round 8
// baseline (speedup 1.0000x reference)
#include <cuda_runtime.h>
#include <cuda_bf16.h>
#include <cstdint>

// Problem constants (fixed by the reference)
#define NQ      256      // number of queries (D)
#define KDIM    256      // descriptor dim (C)
#define KHALF   128      // GEMM partial-K (screen); rest bounded by Cauchy-Schwarz
#define DBP     257      // places_db row pitch in floats (256 dims + id)
#define NT      64       // db rows per tile
#define THREADS 512
#define MAXH    1024
#define MIN_SIM_F 0.8f
#define SCAN_BASE 0.77f  // 0.8 minus margin for bf16 GEMM + bf16 norm errors
#define TOPK    10
#define GRID_SMS 152

#define APITCH  136      // bf16 row pitch for K=128 (272B rows: LDSM conflict-free)
#define BPITCH  136
#define A_BYTES (NQ * APITCH * 2)      // 69632
#define B_BYTES (NT * BPITCH * 2)      // 17408
#define THR_OFF (A_BYTES + B_BYTES)
#define QT_OFF  (THR_OFF + NT * 4)
#define SMEM_TOTAL (QT_OFF + NQ * 4 + 16)

// Scratch (device globals — no allocations allowed)
__device__ int g_hitCnt[NQ];
__device__ int g_hitIdx[NQ * MAXH];

__global__ void init_kernel() {
    if (threadIdx.x < NQ) g_hitCnt[threadIdx.x] = 0;
}

__device__ __forceinline__ uint32_t smem_u32(const void* p) {
    uint32_t a;
    asm("{ .reg .u64 t; cvta.to.shared.u64 t, %1; cvt.u32.u64 %0, t; }" : "=r"(a) : "l"(p));
    return a;
}

#define LDSM4(r0, r1, r2, r3, addr) \
    asm volatile("ldmatrix.sync.aligned.m8n8.x4.shared.b16 {%0,%1,%2,%3}, [%4];" \
        : "=r"(r0), "=r"(r1), "=r"(r2), "=r"(r3) : "r"(addr))

__device__ __forceinline__ void mma_bf16(float* acc, uint32_t a0, uint32_t a1,
                                         uint32_t a2, uint32_t a3,
                                         uint32_t b0, uint32_t b1) {
    asm volatile(
        "mma.sync.aligned.m16n8k16.row.col.f32.bf16.bf16.f32 "
        "{%0,%1,%2,%3}, {%4,%5,%6,%7}, {%8,%9}, {%0,%1,%2,%3};\n"
        : "+f"(acc[0]), "+f"(acc[1]), "+f"(acc[2]), "+f"(acc[3])
        : "r"(a0), "r"(a1), "r"(a2), "r"(a3), "r"(b0), "r"(b1));
}

// ---------------------------------------------------------------------------
// bf16 mma.sync GEMM over K=128 + Cauchy-Schwarz screened threshold scan.
// flag (m,n) iff  q1.x1 >= 0.77 - q2max * ||x2_n||   (superset of sim>=0.8)
// ---------------------------------------------------------------------------
__global__ void __launch_bounds__(THREADS, 1)
gemm_scan_kernel(const float* __restrict__ desc,
                 const float* __restrict__ db,
                 int ndb, int ntiles)
{
    extern __shared__ __align__(16) unsigned char smem[];
    __nv_bfloat16* As   = reinterpret_cast<__nv_bfloat16*>(smem);   // [NQ][APITCH]
    __nv_bfloat16* Bs   = As + NQ * APITCH;                         // [NT][BPITCH]
    float*         thrS = reinterpret_cast<float*>(smem + THR_OFF); // [NT]
    float*         qtmp = reinterpret_cast<float*>(smem + QT_OFF);  // [NQ] then [0]=q2max

    const int tid  = threadIdx.x;
    const int lane = tid & 31;
    const int warp = tid >> 5;   // 0..15
    const int wm   = warp >> 1;  // 0..7  : M rows [wm*32, wm*32+32)
    const int wn   = warp & 1;   // 0..1  : N cols [wn*32, wn*32+32)

    // ---- Convert A (descriptors, f32 -> bf16 smem), only k < 128 ----
    {
        const float4* A4 = reinterpret_cast<const float4*>(desc);
        #pragma unroll 4
        for (int i = tid; i < (NQ * KDIM) / 4; i += THREADS) {
            float4 v = A4[i];
            int e = i * 4;
            int r = e >> 8;
            int c = e & 255;
            if (c < KHALF) {
                __nv_bfloat162* p = reinterpret_cast<__nv_bfloat162*>(As + r * APITCH + c);
                p[0] = __floats2bfloat162_rn(v.x, v.y);
                p[1] = __floats2bfloat162_rn(v.z, v.w);
            }
        }
    }
    __syncthreads();

    // ---- One-time: q2max = max_m sqrt(1 - ||q1_m||^2) ----
    {
        int qr = tid >> 1, qs = tid & 1;
        const __nv_bfloat162* rp =
            reinterpret_cast<const __nv_bfloat162*>(As + qr * APITCH) + qs * 32;
        float s = 0.f;
        #pragma unroll
        for (int j = 0; j < 32; j++) {
            float2 f = __bfloat1622float2(rp[j]);
            s = fmaf(f.x, f.x, s); s = fmaf(f.y, f.y, s);
        }
        s += __shfl_xor_sync(0xffffffffu, s, 1);
        if (qs == 0) qtmp[qr] = sqrtf(fmaxf(1.f - s, 0.f));
        __syncthreads();
        if (tid < 32) {
            float m = 0.f;
            #pragma unroll
            for (int j = 0; j < 8; j++) m = fmaxf(m, qtmp[tid * 8 + j]);
            #pragma unroll
            for (int o = 16; o; o >>= 1) m = fmaxf(m, __shfl_xor_sync(0xffffffffu, m, o));
            if (tid == 0) qtmp[0] = m;
        }
        __syncthreads();
    }
    const float q2max = qtmp[0];

    // ---- Per-lane ldmatrix base addresses ----
    const uint32_t smem_base = smem_u32(smem);
    const uint32_t Bs_base   = smem_base + A_BYTES;
    const int g  = lane >> 3;
    const int lr = lane & 7;
    uint32_t a_addr[2];
    #pragma unroll
    for (int mi = 0; mi < 2; mi++)
        a_addr[mi] = smem_base +
            (uint32_t)(((wm * 32 + mi * 16 + (g & 1) * 8 + lr) * APITCH + (g >> 1) * 8) * 2);
    uint32_t b_addr[2];
    #pragma unroll
    for (int h = 0; h < 2; h++)
        b_addr[h] = Bs_base +
            (uint32_t)(((wn * 32 + h * 16 + (g >> 1) * 8 + lr) * BPITCH + (g & 1) * 8) * 2);

    // ---- Stage tile 0 (contiguous float4 stream over the whole 64x257 tile) ----
    float4 st[9];
    const int NF4 = (NT * DBP) / 4;   // 4112
    int t = blockIdx.x;
    if (t < ntiles) {
        const float4* B4 = reinterpret_cast<const float4*>(db + (size_t)t * (NT * DBP));
        int nf4 = (min(NT, ndb - t * NT) * DBP) >> 2;
        #pragma unroll
        for (int it = 0; it < 9; it++) {
            int i = tid + it * THREADS;
            st[it] = (i < nf4) ? B4[i] : make_float4(0.f, 0.f, 0.f, 0.f);
        }
    }

    for (; t < ntiles; t += gridDim.x) {
        __syncthreads();  // prev tile's readers of Bs/thrS done

        // 1) convert staged regs -> Bs (bf16), only cols < 128
        #pragma unroll
        for (int it = 0; it < 9; it++) {
            int i = tid + it * THREADS;
            if (i < NF4) {
                int e = i * 4;
                int r = e / DBP;
                int c = e - r * DBP;
                float v[4] = { st[it].x, st[it].y, st[it].z, st[it].w };
                #pragma unroll
                for (int j = 0; j < 4; j++) {
                    if (c < KHALF) Bs[r * BPITCH + c] = __float2bfloat16(v[j]);
                    if (++c == DBP) { c = 0; r++; }
                }
            }
        }
        __syncthreads();  // Bs ready

        // 2) stage next tile (LDGs in flight across norms + MMA + epilogue)
        int nxt = t + gridDim.x;
        if (nxt < ntiles) {
            const float4* B4 = reinterpret_cast<const float4*>(db + (size_t)nxt * (NT * DBP));
            int nf4 = (min(NT, ndb - nxt * NT) * DBP) >> 2;
            #pragma unroll
            for (int it = 0; it < 9; it++) {
                int i = tid + it * THREADS;
                st[it] = (i < nf4) ? B4[i] : make_float4(0.f, 0.f, 0.f, 0.f);
            }
        }

        // 3) per-row thresholds: thr[n] = 0.77 - q2max * sqrt(1 - ||x1_n||^2)
        {
            int nr = tid >> 3, sub = tid & 7;   // 8 threads per row
            const __nv_bfloat162* rp =
                reinterpret_cast<const __nv_bfloat162*>(Bs + nr * BPITCH) + sub * 8;
            float s = 0.f;
            #pragma unroll
            for (int j = 0; j < 8; j++) {
                float2 f = __bfloat1622float2(rp[j]);
                s = fmaf(f.x, f.x, s); s = fmaf(f.y, f.y, s);
            }
            #pragma unroll
            for (int o = 4; o; o >>= 1) s += __shfl_xor_sync(0xffffffffu, s, o);
            if (sub == 0)
                thrS[nr] = SCAN_BASE - q2max * sqrtf(fmaxf(1.f - s, 0.f));
        }
        __syncthreads();  // thrS ready

        // 4) MMA compute: warp tile 32(M) x 32(N), K=128
        float acc[2][4][4];
        #pragma unroll
        for (int mi = 0; mi < 2; mi++)
            #pragma unroll
            for (int ni = 0; ni < 4; ni++)
                #pragma unroll
                for (int cc = 0; cc < 4; cc++) acc[mi][ni][cc] = 0.f;

        #pragma unroll
        for (int ks = 0; ks < 8; ks++) {
            const uint32_t koff = (uint32_t)(ks * 32);   // 16 bf16 = 32 bytes
            uint32_t a[2][4], bb[2][4];
            LDSM4(a[0][0], a[0][1], a[0][2], a[0][3], a_addr[0] + koff);
            LDSM4(a[1][0], a[1][1], a[1][2], a[1][3], a_addr[1] + koff);
            LDSM4(bb[0][0], bb[0][1], bb[0][2], bb[0][3], b_addr[0] + koff);
            LDSM4(bb[1][0], bb[1][1], bb[1][2], bb[1][3], b_addr[1] + koff);
            #pragma unroll
            for (int mi = 0; mi < 2; mi++) {
                mma_bf16(acc[mi][0], a[mi][0], a[mi][1], a[mi][2], a[mi][3], bb[0][0], bb[0][1]);
                mma_bf16(acc[mi][1], a[mi][0], a[mi][1], a[mi][2], a[mi][3], bb[0][2], bb[0][3]);
                mma_bf16(acc[mi][2], a[mi][0], a[mi][1], a[mi][2], a[mi][3], bb[1][0], bb[1][1]);
                mma_bf16(acc[mi][3], a[mi][0], a[mi][1], a[mi][2], a[mi][3], bb[1][2], bb[1][3]);
            }
        }

        // 5) Epilogue: per-n screened compare; rare append (exact recompute later)
        const int row0 = t * NT;
        #pragma unroll
        for (int ni = 0; ni < 4; ni++) {
            #pragma unroll
            for (int p = 0; p < 2; p++) {
                float mx = fmaxf(fmaxf(acc[0][ni][p], acc[0][ni][p + 2]),
                                 fmaxf(acc[1][ni][p], acc[1][ni][p + 2]));
                int nl = wn * 32 + ni * 8 + ((lane & 3) << 1) + p;
                float th = thrS[nl];
                if (mx >= th) {
                    int n = row0 + nl;
                    if (n < ndb) {
                        #pragma unroll
                        for (int mi = 0; mi < 2; mi++)
                            #pragma unroll
                            for (int ph = 0; ph < 2; ph++) {
                                if (acc[mi][ni][p + ph * 2] >= th) {
                                    int m = wm * 32 + mi * 16 + ph * 8 + (lane >> 2);
                                    int pos = atomicAdd(&g_hitCnt[m], 1);
                                    if (pos < MAXH) g_hitIdx[m * MAXH + pos] = n;
                                }
                            }
                    }
                }
            }
        }
    }
}

// ---------------------------------------------------------------------------
// Finalize: exact fp32 recompute of candidates, top-10 (sim desc, idx asc),
// voting, box removal, sim_scores, output assembly. One CTA, 256 threads.
// ---------------------------------------------------------------------------
__global__ void finalize_kernel(const float* __restrict__ boxes,
                                const float* __restrict__ desc,
                                const float* __restrict__ db,
                                float* __restrict__ out)
{
    const int d = threadIdx.x;  // one thread per query / box
    __shared__ float sx1[NQ], sy1[NQ], sx2[NQ], sy2[NQ], sarea[NQ];
    __shared__ int   slbl[NQ];

    // --- exact recompute + top-10 insertion (sim desc, db-index asc) ---
    float ts[TOPK];
    int   tn[TOPK];
    int cnt = g_hitCnt[d];
    if (cnt > MAXH) cnt = MAXH;
    int K = 0;
    for (int i = 0; i < cnt; i++) {
        int n = g_hitIdx[d * MAXH + i];
        float s = 0.f;
        const float* qa = desc + (size_t)d * KDIM;
        const float* xb = db + (size_t)n * DBP;
        for (int k = 0; k < KDIM; k++) s = fmaf(qa[k], xb[k], s);
        if (s < MIN_SIM_F) continue;
        int p = K;
        while (p > 0 && (s > ts[p - 1] || (s == ts[p - 1] && n < tn[p - 1]))) p--;
        if (p < TOPK) {
            int end = (K < TOPK) ? K : (TOPK - 1);
            for (int q = end; q > p; q--) { ts[q] = ts[q - 1]; tn[q] = tn[q - 1]; }
            ts[p] = s; tn[p] = n;
            if (K < TOPK) K++;
        }
    }

    // --- voting: max count; ties -> smallest class id ---
    int ids[TOPK];
    for (int kk = 0; kk < K; kk++)
        ids[kk] = (int)db[(size_t)tn[kk] * DBP + (DBP - 1)];
    int best_cnt = 0, best_id = 0x7fffffff;
    for (int kk = 0; kk < K; kk++) {
        int c = 0;
        for (int j = 0; j < K; j++) c += (ids[j] == ids[kk]);
        if (c > best_cnt || (c == best_cnt && ids[kk] < best_id)) {
            best_cnt = c; best_id = ids[kk];
        }
    }
    int label = (best_cnt > 0) ? best_id : -1;

    // --- box overlap removal ---
    float x1 = boxes[d * 4 + 0], y1 = boxes[d * 4 + 1];
    float x2 = boxes[d * 4 + 2], y2 = boxes[d * 4 + 3];
    float area = (x2 - x1) * (y2 - y1);
    sx1[d] = x1; sy1[d] = y1; sx2[d] = x2; sy2[d] = y2;
    sarea[d] = area; slbl[d] = label;
    __syncthreads();

    bool removed = false;
    if (label >= 0) {
        for (int j = 0; j < NQ; j++) {
            if (j == d || slbl[j] != label) continue;
            float ix1 = fmaxf(x1, sx1[j]);
            float iy1 = fmaxf(y1, sy1[j]);
            float ix2 = fminf(x2, sx2[j]);
            float iy2 = fminf(y2, sy2[j]);
            float inter = fmaxf(ix2 - ix1, 0.f) * fmaxf(iy2 - iy1, 0.f);
            float asmall = fminf(area, sarea[j]);
            float ov = (asmall > 0.f) ? (inter / asmall) : 0.f;
            if (ov >= 0.8f && sarea[j] <= area) removed = true;
        }
    }
    int result = removed ? -1 : label;

    float score = 0.f;
    for (int kk = 0; kk < K; kk++)
        if (ids[kk] == result) score = fmaxf(score, ts[kk]);

    for (int i = d; i < NQ * 4; i += NQ) out[i] = boxes[i];
    out[NQ * 4 + d] = score;
    out[NQ * 5 + d] = (float)result;
}

// ---------------------------------------------------------------------------
extern "C" void kernel_launch(void* const* d_in, const int* in_sizes, int n_in,
                              void* d_out, int out_size)
{
    const float* boxes = (const float*)d_in[0];
    const float* desc  = (const float*)d_in[1];
    const float* db    = (const float*)d_in[2];
    int db_elems = in_sizes[2];
    for (int i = 0; i < n_in; i++) {
        if (in_sizes[i] == NQ * 4)         boxes = (const float*)d_in[i];
        else if (in_sizes[i] == NQ * KDIM) desc  = (const float*)d_in[i];
        else                               { db = (const float*)d_in[i]; db_elems = in_sizes[i]; }
    }
    int ndb    = db_elems / DBP;
    int ntiles = (ndb + NT - 1) / NT;

    cudaFuncSetAttribute(gemm_scan_kernel,
                         cudaFuncAttributeMaxDynamicSharedMemorySize, SMEM_TOTAL);

    init_kernel<<<1, 256>>>();
    gemm_scan_kernel<<<GRID_SMS, THREADS, SMEM_TOTAL>>>(desc, db, ndb, ntiles);
    finalize_kernel<<<1, NQ>>>(boxes, desc, db, (float*)d_out);
    (void)out_size;
}